// round 4
// baseline (speedup 1.0000x reference)
#include <cuda_runtime.h>
#include <cuda_bf16.h>
#include <math.h>

// Problem constants (fixed by the dataset)
#define B   32
#define H   16
#define D   128
#define KV  2048
#define E   2048          // H*D
#define E3  6144          // 3*E
#define KV1 2049          // KV+1
#define KV1P 2052         // KV1 padded to multiple of 4 (keeps smem 16B-aligned)

// Scratch (device globals: allocation-free rule)
__device__ __align__(16) float g_qkv[B * E3];   // QKV projection result (B, 3E)
__device__ __align__(16) float g_ctx[B * E];    // attention context (B, E)

// ---------------------------------------------------------------------------
// Skinny GEMM: Y[32, N] = X[32, K] @ W[K, N] + bias[N]
// Block: 256 threads, 32 output columns. Each warp owns 4 rows (warpId*4..+3),
// each lane one column. X tile staged in smem (broadcast reads within warp),
// W streamed from global (coalesced per warp, L1 broadcast across warps).
// ---------------------------------------------------------------------------
__global__ void gemm32_kernel(const float* __restrict__ X,
                              const float* __restrict__ W,
                              const float* __restrict__ bias,
                              float* __restrict__ Y,
                              int K, int N)
{
    __shared__ __align__(16) float xs[32][32];

    const int tid = threadIdx.x;
    const int col = blockIdx.x * 32 + (tid & 31);
    const int rg  = tid >> 5;          // warp id -> row group
    const int r0  = rg * 4;

    float acc0 = 0.f, acc1 = 0.f, acc2 = 0.f, acc3 = 0.f;

    for (int k0 = 0; k0 < K; k0 += 32) {
        // stage X tile [32 rows][32 k]
        #pragma unroll
        for (int i = 0; i < 4; i++) {
            int idx = tid + i * 256;
            int bb  = idx >> 5;
            int kk  = idx & 31;
            xs[bb][kk] = X[(size_t)bb * K + k0 + kk];
        }
        __syncthreads();

        #pragma unroll
        for (int kk = 0; kk < 32; kk += 4) {
            const float4 x0 = *(const float4*)&xs[r0 + 0][kk];
            const float4 x1 = *(const float4*)&xs[r0 + 1][kk];
            const float4 x2 = *(const float4*)&xs[r0 + 2][kk];
            const float4 x3 = *(const float4*)&xs[r0 + 3][kk];
            const float w0 = W[(size_t)(k0 + kk + 0) * N + col];
            const float w1 = W[(size_t)(k0 + kk + 1) * N + col];
            const float w2 = W[(size_t)(k0 + kk + 2) * N + col];
            const float w3 = W[(size_t)(k0 + kk + 3) * N + col];

            acc0 += x0.x * w0; acc0 += x0.y * w1; acc0 += x0.z * w2; acc0 += x0.w * w3;
            acc1 += x1.x * w0; acc1 += x1.y * w1; acc1 += x1.z * w2; acc1 += x1.w * w3;
            acc2 += x2.x * w0; acc2 += x2.y * w1; acc2 += x2.z * w2; acc2 += x2.w * w3;
            acc3 += x3.x * w0; acc3 += x3.y * w1; acc3 += x3.z * w2; acc3 += x3.w * w3;
        }
        __syncthreads();
    }

    const float bv = bias[col];
    Y[(size_t)(r0 + 0) * N + col] = acc0 + bv;
    Y[(size_t)(r0 + 1) * N + col] = acc1 + bv;
    Y[(size_t)(r0 + 2) * N + col] = acc2 + bv;
    Y[(size_t)(r0 + 3) * N + col] = acc3 + bv;
}

// ---------------------------------------------------------------------------
// Fused attention + KV-cache concat. One block per (b, h). 256 threads.
// Pass 1: stream K rows: compute q.k AND write row into Kc output.
// Softmax over 2049 scores in smem.
// Pass 2: stream V rows (8-way k-split over warps): accumulate ctx AND write Vc.
// ---------------------------------------------------------------------------
__global__ void attn_kernel(const float* __restrict__ kcache,
                            const float* __restrict__ vcache,
                            const float* __restrict__ mask,
                            float* __restrict__ out_Kc,
                            float* __restrict__ out_Vc,
                            float* __restrict__ out_mask)
{
    __shared__ __align__(16) float q_sm[D];
    __shared__ __align__(16) float sc[KV1P];      // scores -> exp weights (padded)
    __shared__ __align__(16) float red[20];       // [0..7] max, [8..15] sum, [16] inv_sum
    __shared__ __align__(16) float cpart[8][D];   // per-warp partial ctx

    const int tid = threadIdx.x;
    const int w   = tid >> 5;
    const int l   = tid & 31;
    const int b   = blockIdx.x >> 4;
    const int h   = blockIdx.x & 15;
    const float scale = 0.08838834764831845f;   // 1/sqrt(128)

    const float* mrow = mask + (size_t)b * KV;

    // mask_new output (one set of blocks handles it)
    if (h == 0) {
        float* mo = out_mask + (size_t)b * KV1;
        for (int k = tid; k < KV; k += 256) mo[k] = mrow[k];
        if (tid == 0) mo[KV] = 1.0f;
    }

    // load q
    if (tid < D) q_sm[tid] = g_qkv[(size_t)b * E3 + h * D + tid];
    __syncthreads();

    const float4 qf = *(const float4*)&q_sm[l * 4];

    const size_t bh = (size_t)b * H + h;
    const float4* Kin  = (const float4*)(kcache + bh * KV * D);
    float4*       Kout = (float4*)(out_Kc + bh * (size_t)KV1 * D);

    // ---- Pass 1: scores + Kc copy. Warp w does keys [kb+4w, kb+4w+3] ----
    for (int kb = w * 4; kb < KV; kb += 32) {
        float4 a0 = Kin[(size_t)(kb + 0) * 32 + l];
        float4 a1 = Kin[(size_t)(kb + 1) * 32 + l];
        float4 a2 = Kin[(size_t)(kb + 2) * 32 + l];
        float4 a3 = Kin[(size_t)(kb + 3) * 32 + l];
        Kout[(size_t)(kb + 0) * 32 + l] = a0;
        Kout[(size_t)(kb + 1) * 32 + l] = a1;
        Kout[(size_t)(kb + 2) * 32 + l] = a2;
        Kout[(size_t)(kb + 3) * 32 + l] = a3;

        float d0 = a0.x * qf.x + a0.y * qf.y + a0.z * qf.z + a0.w * qf.w;
        float d1 = a1.x * qf.x + a1.y * qf.y + a1.z * qf.z + a1.w * qf.w;
        float d2 = a2.x * qf.x + a2.y * qf.y + a2.z * qf.z + a2.w * qf.w;
        float d3 = a3.x * qf.x + a3.y * qf.y + a3.z * qf.z + a3.w * qf.w;
        #pragma unroll
        for (int off = 16; off > 0; off >>= 1) {
            d0 += __shfl_xor_sync(0xFFFFFFFFu, d0, off);
            d1 += __shfl_xor_sync(0xFFFFFFFFu, d1, off);
            d2 += __shfl_xor_sync(0xFFFFFFFFu, d2, off);
            d3 += __shfl_xor_sync(0xFFFFFFFFu, d3, off);
        }
        if (l < 4) {
            float dv = (l == 0) ? d0 : (l == 1) ? d1 : (l == 2) ? d2 : d3;
            float m  = mrow[kb + l];
            sc[kb + l] = (m == 0.0f) ? -1e30f : dv * scale;
        }
    }

    // new key: from qkv scratch, also write Kc row 2048
    if (w == 0) {
        float4 kn = *(const float4*)&g_qkv[(size_t)b * E3 + E + h * D + l * 4];
        Kout[(size_t)KV * 32 + l] = kn;
        float dn = kn.x * qf.x + kn.y * qf.y + kn.z * qf.z + kn.w * qf.w;
        #pragma unroll
        for (int off = 16; off > 0; off >>= 1)
            dn += __shfl_xor_sync(0xFFFFFFFFu, dn, off);
        if (l == 0) sc[KV] = dn * scale;   // new token never masked
    }
    __syncthreads();

    // ---- Softmax over sc[0..2048] ----
    float mx = -1e30f;
    for (int k = tid; k < KV1; k += 256) mx = fmaxf(mx, sc[k]);
    #pragma unroll
    for (int off = 16; off > 0; off >>= 1)
        mx = fmaxf(mx, __shfl_xor_sync(0xFFFFFFFFu, mx, off));
    if (l == 0) red[w] = mx;
    __syncthreads();
    if (tid == 0) {
        float m = red[0];
        #pragma unroll
        for (int i = 1; i < 8; i++) m = fmaxf(m, red[i]);
        red[0] = m;
    }
    __syncthreads();
    const float M = red[0];

    float ls = 0.f;
    for (int k = tid; k < KV1; k += 256) {
        float e = __expf(sc[k] - M);
        sc[k] = e;
        ls += e;
    }
    #pragma unroll
    for (int off = 16; off > 0; off >>= 1)
        ls += __shfl_xor_sync(0xFFFFFFFFu, ls, off);
    if (l == 0) red[8 + w] = ls;
    __syncthreads();
    if (tid == 0) {
        float s = 0.f;
        #pragma unroll
        for (int i = 0; i < 8; i++) s += red[8 + i];
        red[16] = 1.0f / s;
    }
    __syncthreads();

    // ---- Pass 2: ctx accumulation + Vc copy. Warp w owns keys [w*256, w*256+256) ----
    const float4* Vin  = (const float4*)(vcache + bh * KV * D);
    float4*       Vout = (float4*)(out_Vc + bh * (size_t)KV1 * D);

    float4 acc = make_float4(0.f, 0.f, 0.f, 0.f);
    const int kstart = w * 256;
    for (int k = kstart; k < kstart + 256; k += 4) {
        float4 v0 = Vin[(size_t)(k + 0) * 32 + l];
        float4 v1 = Vin[(size_t)(k + 1) * 32 + l];
        float4 v2 = Vin[(size_t)(k + 2) * 32 + l];
        float4 v3 = Vin[(size_t)(k + 3) * 32 + l];
        float p0 = sc[k + 0], p1 = sc[k + 1], p2 = sc[k + 2], p3 = sc[k + 3];
        Vout[(size_t)(k + 0) * 32 + l] = v0;
        Vout[(size_t)(k + 1) * 32 + l] = v1;
        Vout[(size_t)(k + 2) * 32 + l] = v2;
        Vout[(size_t)(k + 3) * 32 + l] = v3;
        acc.x += p0 * v0.x; acc.y += p0 * v0.y; acc.z += p0 * v0.z; acc.w += p0 * v0.w;
        acc.x += p1 * v1.x; acc.y += p1 * v1.y; acc.z += p1 * v1.z; acc.w += p1 * v1.w;
        acc.x += p2 * v2.x; acc.y += p2 * v2.y; acc.z += p2 * v2.z; acc.w += p2 * v2.w;
        acc.x += p3 * v3.x; acc.y += p3 * v3.y; acc.z += p3 * v3.z; acc.w += p3 * v3.w;
    }
    if (w == 7) {
        // new value row: from qkv scratch, also write Vc row 2048
        float4 vn = *(const float4*)&g_qkv[(size_t)b * E3 + 2 * E + h * D + l * 4];
        Vout[(size_t)KV * 32 + l] = vn;
        float p = sc[KV];
        acc.x += p * vn.x; acc.y += p * vn.y; acc.z += p * vn.z; acc.w += p * vn.w;
    }
    *(float4*)&cpart[w][l * 4] = acc;
    __syncthreads();

    if (tid < D) {
        float s = 0.f;
        #pragma unroll
        for (int i = 0; i < 8; i++) s += cpart[i][tid];
        g_ctx[(size_t)b * E + h * D + tid] = s * red[16];
    }
}

// ---------------------------------------------------------------------------
extern "C" void kernel_launch(void* const* d_in, const int* in_sizes, int n_in,
                              void* d_out, int out_size)
{
    const float* X      = (const float*)d_in[0];
    const float* kcache = (const float*)d_in[1];
    const float* vcache = (const float*)d_in[2];
    const float* mask   = (const float*)d_in[3];
    const float* Wqkv   = (const float*)d_in[4];
    const float* bqkv   = (const float*)d_in[5];
    const float* Wo     = (const float*)d_in[6];
    const float* bo     = (const float*)d_in[7];

    float* out_O  = (float*)d_out;                              // (B, 1, E)
    float* out_Kc = out_O  + (size_t)B * E;                     // (B, H, KV1, D)
    float* out_Vc = out_Kc + (size_t)B * H * KV1 * D;           // (B, H, KV1, D)
    float* out_mk = out_Vc + (size_t)B * H * KV1 * D;           // (B, KV1)

    float* qkv;  cudaGetSymbolAddress((void**)&qkv,  g_qkv);
    float* ctx;  cudaGetSymbolAddress((void**)&ctx,  g_ctx);

    // 1) QKV projection: (32,2048) @ (2048,6144) + bias
    gemm32_kernel<<<E3 / 32, 256>>>(X, Wqkv, bqkv, qkv, E, E3);

    // 2) Fused attention + cache concat + mask_new
    attn_kernel<<<B * H, 256>>>(kcache, vcache, mask, out_Kc, out_Vc, out_mk);

    // 3) Output projection: (32,2048) @ (2048,2048) + bias
    gemm32_kernel<<<E / 32, 256>>>(ctx, Wo, bo, out_O, E, E);
}

// round 5
// speedup vs baseline: 1.2689x; 1.2689x over previous
#include <cuda_runtime.h>
#include <cuda_bf16.h>
#include <math.h>

// Problem constants (fixed by the dataset)
#define B   32
#define H   16
#define D   128
#define KV  2048
#define E   2048          // H*D
#define E3  6144          // 3*E
#define KV1 2049          // KV+1
#define KV1P 2052         // KV1 padded (keeps smem 16B-aligned)
#define KS  256           // GEMM split-K slice length

// Scratch (device globals: allocation-free rule)
__device__ __align__(16) float g_qkv[B * E3];   // QKV projection result (B, 3E)
__device__ __align__(16) float g_ctx[B * E];    // attention context (B, E)

// ---------------------------------------------------------------------------
// Init: seed atomic-accumulated outputs with bias; emit mask_new.
// Must run first every call (graph replays re-accumulate).
// ---------------------------------------------------------------------------
__global__ void init_kernel(const float* __restrict__ bqkv,
                            const float* __restrict__ bo,
                            const float* __restrict__ mask,
                            float* __restrict__ qkv,
                            float* __restrict__ outO,
                            float* __restrict__ outmask)
{
    const int i = blockIdx.x * blockDim.x + threadIdx.x;
    const int stride = gridDim.x * blockDim.x;
    for (int j = i; j < B * E3; j += stride) qkv[j] = bqkv[j % E3];
    for (int j = i; j < B * E;  j += stride) outO[j] = bo[j & (E - 1)];
    for (int j = i; j < B * KV1; j += stride) {
        int b = j / KV1, k = j - b * KV1;
        outmask[j] = (k == KV) ? 1.0f : mask[b * KV + k];
    }
}

// ---------------------------------------------------------------------------
// Split-K skinny GEMM: Y[32, N] += X[32, K-slice] @ W[K-slice, N]
// grid = (N/128, K/KS). 256 threads. Lane = output row (0..31); warp owns 16
// distinct columns (4x float4, lane-broadcast LDG). X slice staged transposed
// in smem once; mainloop is barrier-free streaming. Epilogue: atomicAdd.
// ---------------------------------------------------------------------------
__global__ void gemm32_split(const float* __restrict__ X,
                             const float* __restrict__ W,
                             float* __restrict__ Y,
                             int K, int N)
{
    __shared__ __align__(16) float xs[KS][33];   // [k][row], padded

    const int tid = threadIdx.x;
    const int l   = tid & 31;          // row
    const int w   = tid >> 5;          // warp -> column group
    const int k0  = blockIdx.y * KS;
    const int cbase = blockIdx.x * 128 + w * 16;

    // Stage X slice transposed: xs[k][row]
    for (int i = tid; i < 32 * (KS / 4); i += 256) {
        const int row = i >> 6;                 // KS/4 = 64
        const int kq  = i & 63;
        const float4 v = *(const float4*)(X + (size_t)row * K + k0 + kq * 4);
        xs[kq * 4 + 0][row] = v.x;
        xs[kq * 4 + 1][row] = v.y;
        xs[kq * 4 + 2][row] = v.z;
        xs[kq * 4 + 3][row] = v.w;
    }
    __syncthreads();

    const float* Wp = W + (size_t)k0 * N + cbase;
    float4 a0 = make_float4(0.f, 0.f, 0.f, 0.f);
    float4 a1 = a0, a2 = a0, a3 = a0;

    #pragma unroll 2
    for (int kk = 0; kk < KS; kk++) {
        const float  x  = xs[kk][l];
        const float4 w0 = *(const float4*)(Wp + 0);
        const float4 w1 = *(const float4*)(Wp + 4);
        const float4 w2 = *(const float4*)(Wp + 8);
        const float4 w3 = *(const float4*)(Wp + 12);
        a0.x += x * w0.x; a0.y += x * w0.y; a0.z += x * w0.z; a0.w += x * w0.w;
        a1.x += x * w1.x; a1.y += x * w1.y; a1.z += x * w1.z; a1.w += x * w1.w;
        a2.x += x * w2.x; a2.y += x * w2.y; a2.z += x * w2.z; a2.w += x * w2.w;
        a3.x += x * w3.x; a3.y += x * w3.y; a3.z += x * w3.z; a3.w += x * w3.w;
        Wp += N;
    }

    float* Yr = Y + (size_t)l * N + cbase;
    atomicAdd(&Yr[0],  a0.x); atomicAdd(&Yr[1],  a0.y);
    atomicAdd(&Yr[2],  a0.z); atomicAdd(&Yr[3],  a0.w);
    atomicAdd(&Yr[4],  a1.x); atomicAdd(&Yr[5],  a1.y);
    atomicAdd(&Yr[6],  a1.z); atomicAdd(&Yr[7],  a1.w);
    atomicAdd(&Yr[8],  a2.x); atomicAdd(&Yr[9],  a2.y);
    atomicAdd(&Yr[10], a2.z); atomicAdd(&Yr[11], a2.w);
    atomicAdd(&Yr[12], a3.x); atomicAdd(&Yr[13], a3.y);
    atomicAdd(&Yr[14], a3.z); atomicAdd(&Yr[15], a3.w);
}

// ---------------------------------------------------------------------------
// Fused attention + KV-cache concat. One block per (b, h). 256 threads.
// Pass 1: stream K rows (8/warp in flight): q.k AND write Kc.
// Softmax over 2049 scores in smem.
// Pass 2: stream V rows (8-way k-split, unroll 8): ctx AND write Vc.
// ---------------------------------------------------------------------------
__global__ void attn_kernel(const float* __restrict__ kcache,
                            const float* __restrict__ vcache,
                            const float* __restrict__ mask,
                            float* __restrict__ out_Kc,
                            float* __restrict__ out_Vc)
{
    __shared__ __align__(16) float q_sm[D];
    __shared__ __align__(16) float sc[KV1P];
    __shared__ __align__(16) float red[20];
    __shared__ __align__(16) float cpart[8][D];

    const int tid = threadIdx.x;
    const int w   = tid >> 5;
    const int l   = tid & 31;
    const int b   = blockIdx.x >> 4;
    const int h   = blockIdx.x & 15;
    const float scale = 0.08838834764831845f;   // 1/sqrt(128)

    const float* mrow = mask + (size_t)b * KV;

    if (tid < D) q_sm[tid] = g_qkv[(size_t)b * E3 + h * D + tid];
    __syncthreads();

    const float4 qf = *(const float4*)&q_sm[l * 4];

    const size_t bh = (size_t)b * H + h;
    const float4* Kin  = (const float4*)(kcache + bh * KV * D);
    float4*       Kout = (float4*)(out_Kc + bh * (size_t)KV1 * D);

    // ---- Pass 1: scores + Kc copy. Warp w does keys [kb, kb+8) ----
    for (int kb = w * 8; kb < KV; kb += 64) {
        float4 a[8];
        #pragma unroll
        for (int j = 0; j < 8; j++) a[j] = Kin[(size_t)(kb + j) * 32 + l];
        #pragma unroll
        for (int j = 0; j < 8; j++) Kout[(size_t)(kb + j) * 32 + l] = a[j];

        float dd[8];
        #pragma unroll
        for (int j = 0; j < 8; j++)
            dd[j] = a[j].x * qf.x + a[j].y * qf.y + a[j].z * qf.z + a[j].w * qf.w;
        #pragma unroll
        for (int j = 0; j < 8; j++) {
            #pragma unroll
            for (int off = 16; off > 0; off >>= 1)
                dd[j] += __shfl_xor_sync(0xFFFFFFFFu, dd[j], off);
        }
        if (l < 8) {
            float dv = dd[l];
            float m  = mrow[kb + l];
            sc[kb + l] = (m == 0.0f) ? -1e30f : dv * scale;
        }
    }

    // new key: from qkv scratch, also write Kc row 2048
    if (w == 0) {
        float4 kn = *(const float4*)&g_qkv[(size_t)b * E3 + E + h * D + l * 4];
        Kout[(size_t)KV * 32 + l] = kn;
        float dn = kn.x * qf.x + kn.y * qf.y + kn.z * qf.z + kn.w * qf.w;
        #pragma unroll
        for (int off = 16; off > 0; off >>= 1)
            dn += __shfl_xor_sync(0xFFFFFFFFu, dn, off);
        if (l == 0) sc[KV] = dn * scale;   // new token never masked
    }
    __syncthreads();

    // ---- Softmax over sc[0..2048] ----
    float mx = -1e30f;
    for (int k = tid; k < KV1; k += 256) mx = fmaxf(mx, sc[k]);
    #pragma unroll
    for (int off = 16; off > 0; off >>= 1)
        mx = fmaxf(mx, __shfl_xor_sync(0xFFFFFFFFu, mx, off));
    if (l == 0) red[w] = mx;
    __syncthreads();
    if (tid == 0) {
        float m = red[0];
        #pragma unroll
        for (int i = 1; i < 8; i++) m = fmaxf(m, red[i]);
        red[0] = m;
    }
    __syncthreads();
    const float M = red[0];

    float ls = 0.f;
    for (int k = tid; k < KV1; k += 256) {
        float e = __expf(sc[k] - M);
        sc[k] = e;
        ls += e;
    }
    #pragma unroll
    for (int off = 16; off > 0; off >>= 1)
        ls += __shfl_xor_sync(0xFFFFFFFFu, ls, off);
    if (l == 0) red[8 + w] = ls;
    __syncthreads();
    if (tid == 0) {
        float s = 0.f;
        #pragma unroll
        for (int i = 0; i < 8; i++) s += red[8 + i];
        red[16] = 1.0f / s;
    }
    __syncthreads();

    // ---- Pass 2: ctx + Vc copy. Warp w owns keys [w*256, w*256+256) ----
    const float4* Vin  = (const float4*)(vcache + bh * KV * D);
    float4*       Vout = (float4*)(out_Vc + bh * (size_t)KV1 * D);

    float4 acc = make_float4(0.f, 0.f, 0.f, 0.f);
    const int kstart = w * 256;
    for (int k = kstart; k < kstart + 256; k += 8) {
        float4 v[8];
        #pragma unroll
        for (int j = 0; j < 8; j++) v[j] = Vin[(size_t)(k + j) * 32 + l];
        #pragma unroll
        for (int j = 0; j < 8; j++) Vout[(size_t)(k + j) * 32 + l] = v[j];
        #pragma unroll
        for (int j = 0; j < 8; j++) {
            const float p = sc[k + j];
            acc.x += p * v[j].x; acc.y += p * v[j].y;
            acc.z += p * v[j].z; acc.w += p * v[j].w;
        }
    }
    if (w == 7) {
        float4 vn = *(const float4*)&g_qkv[(size_t)b * E3 + 2 * E + h * D + l * 4];
        Vout[(size_t)KV * 32 + l] = vn;
        float p = sc[KV];
        acc.x += p * vn.x; acc.y += p * vn.y; acc.z += p * vn.z; acc.w += p * vn.w;
    }
    *(float4*)&cpart[w][l * 4] = acc;
    __syncthreads();

    if (tid < D) {
        float s = 0.f;
        #pragma unroll
        for (int i = 0; i < 8; i++) s += cpart[i][tid];
        g_ctx[(size_t)b * E + h * D + tid] = s * red[16];
    }
}

// ---------------------------------------------------------------------------
extern "C" void kernel_launch(void* const* d_in, const int* in_sizes, int n_in,
                              void* d_out, int out_size)
{
    const float* X      = (const float*)d_in[0];
    const float* kcache = (const float*)d_in[1];
    const float* vcache = (const float*)d_in[2];
    const float* mask   = (const float*)d_in[3];
    const float* Wqkv   = (const float*)d_in[4];
    const float* bqkv   = (const float*)d_in[5];
    const float* Wo     = (const float*)d_in[6];
    const float* bo     = (const float*)d_in[7];

    float* out_O  = (float*)d_out;                              // (B, 1, E)
    float* out_Kc = out_O  + (size_t)B * E;                     // (B, H, KV1, D)
    float* out_Vc = out_Kc + (size_t)B * H * KV1 * D;           // (B, H, KV1, D)
    float* out_mk = out_Vc + (size_t)B * H * KV1 * D;           // (B, KV1)

    float* qkv;  cudaGetSymbolAddress((void**)&qkv,  g_qkv);
    float* ctx;  cudaGetSymbolAddress((void**)&ctx,  g_ctx);

    // 0) Seed outputs with bias (atomics accumulate on top), emit mask_new
    init_kernel<<<256, 256>>>(bqkv, bo, mask, qkv, out_O, out_mk);

    // 1) QKV projection: (32,2048) @ (2048,6144), split-K atomic
    gemm32_split<<<dim3(E3 / 128, E / KS), 256>>>(X, Wqkv, qkv, E, E3);

    // 2) Fused attention + cache concat
    attn_kernel<<<B * H, 256>>>(kcache, vcache, mask, out_Kc, out_Vc);

    // 3) Output projection: (32,2048) @ (2048,2048), split-K atomic
    gemm32_split<<<dim3(E / 128, E / KS), 256>>>(ctx, Wo, out_O, E, E);
}

// round 6
// speedup vs baseline: 1.8665x; 1.4709x over previous
#include <cuda_runtime.h>
#include <cuda_bf16.h>
#include <math.h>

// Problem constants (fixed by the dataset)
#define B   32
#define H   16
#define D   128
#define KV  2048
#define E   2048          // H*D
#define E3  6144          // 3*E
#define KV1 2049          // KV+1
#define KV1P 2052         // KV1 padded (keeps smem 16B-aligned)
#define GK  64            // GEMM split-K slice length

// Scratch (device globals: allocation-free rule)
__device__ __align__(16) float g_qkv[B * E3];   // QKV projection result (B, 3E)
__device__ __align__(16) float g_ctx[B * E];    // attention context (B, E)

// ---------------------------------------------------------------------------
// Init: seed atomic-accumulated outputs with bias; emit mask_new.
// Must run first every call (graph replays re-accumulate).
// ---------------------------------------------------------------------------
__global__ void init_kernel(const float* __restrict__ bqkv,
                            const float* __restrict__ bo,
                            const float* __restrict__ mask,
                            float* __restrict__ qkv,
                            float* __restrict__ outO,
                            float* __restrict__ outmask)
{
    const int i = blockIdx.x * blockDim.x + threadIdx.x;
    const int stride = gridDim.x * blockDim.x;
    for (int j = i; j < B * E3; j += stride) qkv[j] = bqkv[j % E3];
    for (int j = i; j < B * E;  j += stride) outO[j] = bo[j & (E - 1)];
    for (int j = i; j < B * KV1; j += stride) {
        int b = j / KV1, k = j - b * KV1;
        outmask[j] = (k == KV) ? 1.0f : mask[b * KV + k];
    }
}

// ---------------------------------------------------------------------------
// Split-K skinny GEMM v2: Y[32, N] += X[32, k-slice] @ W[k-slice, N]
// grid = (N/256, K/GK), 256 threads. Thread = one output column:
//   - W loads are fully coalesced (warp reads a 128B line per k)
//   - 32 row-accumulators in registers
//   - X tile (32 x GK) staged in smem, read lane-uniform (broadcast)
// Epilogue: atomicAdd into bias-seeded Y.
// ---------------------------------------------------------------------------
__global__ void __launch_bounds__(256, 4)
gemm32_v2(const float* __restrict__ X,
          const float* __restrict__ W,
          float* __restrict__ Y,
          int K, int N)
{
    __shared__ __align__(16) float xs[32][GK];

    const int tid = threadIdx.x;
    const int col = blockIdx.x * 256 + tid;
    const int k0  = blockIdx.y * GK;

    // stage X[0:32][k0:k0+GK]: 32*GK floats = 512 float4, 2 per thread
    #pragma unroll
    for (int f = tid; f < 32 * GK / 4; f += 256) {
        const int row = f >> 4;           // GK/4 = 16 float4 per row
        const int kq  = f & 15;
        *(float4*)&xs[row][kq * 4] =
            *(const float4*)(X + (size_t)row * K + k0 + kq * 4);
    }
    __syncthreads();

    float acc[32];
    #pragma unroll
    for (int r = 0; r < 32; r++) acc[r] = 0.f;

    const float* Wp = W + (size_t)k0 * N + col;

    #pragma unroll 2
    for (int kk = 0; kk < GK; kk += 4) {
        const float w0 = Wp[(size_t)(kk + 0) * N];
        const float w1 = Wp[(size_t)(kk + 1) * N];
        const float w2 = Wp[(size_t)(kk + 2) * N];
        const float w3 = Wp[(size_t)(kk + 3) * N];
        #pragma unroll
        for (int r = 0; r < 32; r++) {
            const float4 x = *(const float4*)&xs[r][kk];
            acc[r] += x.x * w0 + x.y * w1 + x.z * w2 + x.w * w3;
        }
    }

    float* Yc = Y + col;
    #pragma unroll
    for (int r = 0; r < 32; r++)
        atomicAdd(Yc + (size_t)r * N, acc[r]);
}

// ---------------------------------------------------------------------------
// Fused attention + KV-cache concat. One block per (b, h). 256 threads.
// Pass 1: stream K rows (8/warp in flight): q.k AND write Kc.
// Softmax over 2049 scores in smem.
// Pass 2: stream V rows (8-way k-split, unroll 8): ctx AND write Vc.
// ---------------------------------------------------------------------------
__global__ void attn_kernel(const float* __restrict__ kcache,
                            const float* __restrict__ vcache,
                            const float* __restrict__ mask,
                            float* __restrict__ out_Kc,
                            float* __restrict__ out_Vc)
{
    __shared__ __align__(16) float q_sm[D];
    __shared__ __align__(16) float sc[KV1P];
    __shared__ __align__(16) float red[20];
    __shared__ __align__(16) float cpart[8][D];

    const int tid = threadIdx.x;
    const int w   = tid >> 5;
    const int l   = tid & 31;
    const int b   = blockIdx.x >> 4;
    const int h   = blockIdx.x & 15;
    const float scale = 0.08838834764831845f;   // 1/sqrt(128)

    const float* mrow = mask + (size_t)b * KV;

    if (tid < D) q_sm[tid] = g_qkv[(size_t)b * E3 + h * D + tid];
    __syncthreads();

    const float4 qf = *(const float4*)&q_sm[l * 4];

    const size_t bh = (size_t)b * H + h;
    const float4* Kin  = (const float4*)(kcache + bh * KV * D);
    float4*       Kout = (float4*)(out_Kc + bh * (size_t)KV1 * D);

    // ---- Pass 1: scores + Kc copy. Warp w does keys [kb, kb+8) ----
    for (int kb = w * 8; kb < KV; kb += 64) {
        float4 a[8];
        #pragma unroll
        for (int j = 0; j < 8; j++) a[j] = Kin[(size_t)(kb + j) * 32 + l];
        #pragma unroll
        for (int j = 0; j < 8; j++) Kout[(size_t)(kb + j) * 32 + l] = a[j];

        float dd[8];
        #pragma unroll
        for (int j = 0; j < 8; j++)
            dd[j] = a[j].x * qf.x + a[j].y * qf.y + a[j].z * qf.z + a[j].w * qf.w;
        #pragma unroll
        for (int j = 0; j < 8; j++) {
            #pragma unroll
            for (int off = 16; off > 0; off >>= 1)
                dd[j] += __shfl_xor_sync(0xFFFFFFFFu, dd[j], off);
        }
        if (l < 8) {
            float dv = dd[l];
            float m  = mrow[kb + l];
            sc[kb + l] = (m == 0.0f) ? -1e30f : dv * scale;
        }
    }

    // new key: from qkv scratch, also write Kc row 2048
    if (w == 0) {
        float4 kn = *(const float4*)&g_qkv[(size_t)b * E3 + E + h * D + l * 4];
        Kout[(size_t)KV * 32 + l] = kn;
        float dn = kn.x * qf.x + kn.y * qf.y + kn.z * qf.z + kn.w * qf.w;
        #pragma unroll
        for (int off = 16; off > 0; off >>= 1)
            dn += __shfl_xor_sync(0xFFFFFFFFu, dn, off);
        if (l == 0) sc[KV] = dn * scale;   // new token never masked
    }
    __syncthreads();

    // ---- Softmax over sc[0..2048] ----
    float mx = -1e30f;
    for (int k = tid; k < KV1; k += 256) mx = fmaxf(mx, sc[k]);
    #pragma unroll
    for (int off = 16; off > 0; off >>= 1)
        mx = fmaxf(mx, __shfl_xor_sync(0xFFFFFFFFu, mx, off));
    if (l == 0) red[w] = mx;
    __syncthreads();
    if (tid == 0) {
        float m = red[0];
        #pragma unroll
        for (int i = 1; i < 8; i++) m = fmaxf(m, red[i]);
        red[0] = m;
    }
    __syncthreads();
    const float M = red[0];

    float ls = 0.f;
    for (int k = tid; k < KV1; k += 256) {
        float e = __expf(sc[k] - M);
        sc[k] = e;
        ls += e;
    }
    #pragma unroll
    for (int off = 16; off > 0; off >>= 1)
        ls += __shfl_xor_sync(0xFFFFFFFFu, ls, off);
    if (l == 0) red[8 + w] = ls;
    __syncthreads();
    if (tid == 0) {
        float s = 0.f;
        #pragma unroll
        for (int i = 0; i < 8; i++) s += red[8 + i];
        red[16] = 1.0f / s;
    }
    __syncthreads();

    // ---- Pass 2: ctx + Vc copy. Warp w owns keys [w*256, w*256+256) ----
    const float4* Vin  = (const float4*)(vcache + bh * KV * D);
    float4*       Vout = (float4*)(out_Vc + bh * (size_t)KV1 * D);

    float4 acc = make_float4(0.f, 0.f, 0.f, 0.f);
    const int kstart = w * 256;
    for (int k = kstart; k < kstart + 256; k += 8) {
        float4 v[8];
        #pragma unroll
        for (int j = 0; j < 8; j++) v[j] = Vin[(size_t)(k + j) * 32 + l];
        #pragma unroll
        for (int j = 0; j < 8; j++) Vout[(size_t)(k + j) * 32 + l] = v[j];
        #pragma unroll
        for (int j = 0; j < 8; j++) {
            const float p = sc[k + j];
            acc.x += p * v[j].x; acc.y += p * v[j].y;
            acc.z += p * v[j].z; acc.w += p * v[j].w;
        }
    }
    if (w == 7) {
        float4 vn = *(const float4*)&g_qkv[(size_t)b * E3 + 2 * E + h * D + l * 4];
        Vout[(size_t)KV * 32 + l] = vn;
        float p = sc[KV];
        acc.x += p * vn.x; acc.y += p * vn.y; acc.z += p * vn.z; acc.w += p * vn.w;
    }
    *(float4*)&cpart[w][l * 4] = acc;
    __syncthreads();

    if (tid < D) {
        float s = 0.f;
        #pragma unroll
        for (int i = 0; i < 8; i++) s += cpart[i][tid];
        g_ctx[(size_t)b * E + h * D + tid] = s * red[16];
    }
}

// ---------------------------------------------------------------------------
extern "C" void kernel_launch(void* const* d_in, const int* in_sizes, int n_in,
                              void* d_out, int out_size)
{
    const float* X      = (const float*)d_in[0];
    const float* kcache = (const float*)d_in[1];
    const float* vcache = (const float*)d_in[2];
    const float* mask   = (const float*)d_in[3];
    const float* Wqkv   = (const float*)d_in[4];
    const float* bqkv   = (const float*)d_in[5];
    const float* Wo     = (const float*)d_in[6];
    const float* bo     = (const float*)d_in[7];

    float* out_O  = (float*)d_out;                              // (B, 1, E)
    float* out_Kc = out_O  + (size_t)B * E;                     // (B, H, KV1, D)
    float* out_Vc = out_Kc + (size_t)B * H * KV1 * D;           // (B, H, KV1, D)
    float* out_mk = out_Vc + (size_t)B * H * KV1 * D;           // (B, KV1)

    float* qkv;  cudaGetSymbolAddress((void**)&qkv,  g_qkv);
    float* ctx;  cudaGetSymbolAddress((void**)&ctx,  g_ctx);

    // 0) Seed outputs with bias (atomics accumulate on top), emit mask_new
    init_kernel<<<256, 256>>>(bqkv, bo, mask, qkv, out_O, out_mk);

    // 1) QKV projection: (32,2048) @ (2048,6144), split-K atomic
    gemm32_v2<<<dim3(E3 / 256, E / GK), 256>>>(X, Wqkv, qkv, E, E3);

    // 2) Fused attention + cache concat
    attn_kernel<<<B * H, 256>>>(kcache, vcache, mask, out_Kc, out_Vc);

    // 3) Output projection: (32,2048) @ (2048,2048), split-K atomic
    gemm32_v2<<<dim3(E / 256, E / GK), 256>>>(ctx, Wo, out_O, E, E);
}